// round 6
// baseline (speedup 1.0000x reference)
#include <cuda_runtime.h>
#include <cuda_bf16.h>
#include <math.h>

// Problem constants
#define NN     50000
#define FIN    256
#define NH     4
#define NR     4
#define FF     64
#define NE     500000
#define CPROJ  1024          // NH*NR*FF
#define CTOT   1280          // CPROJ + NH*FF (skip)
#define NSEG   (NN * NR)     // 200000 (trg, rel) segments
#define NB1    ((NSEG + 1023) / 1024)   // 196 scan blocks

// ---------------- scratch (device globals; no allocation allowed) ----------------
__device__ float         g_ps[(size_t)NN * CTOT];          // [n][1280]: proj | skip (fp32)
__device__ float         g_agg[(size_t)NN * NR * NH * FF]; // [((n*4+r)*4+h)*64+f]
__device__ float         g_ssrc[(size_t)NN * NH * NR];     // [n*16 + h*4 + r]
__device__ float         g_strg[(size_t)NN * NH * NR];
__device__ unsigned      g_m_u[NR * NH];
__device__ __nv_bfloat16 g_aext[(size_t)NN * 512];         // [n][512] = [x_hi(256) | x_lo(256)]
__device__ __nv_bfloat16 g_bext[(size_t)CTOT * 512];       // [c][512] = [W_hi | W_lo]
// edge sort scratch
__device__ int           g_cnt[NSEG];
__device__ int           g_off[NSEG + 1];
__device__ int           g_cur[NSEG];
__device__ int           g_bsum[256];
__device__ int           g_psrc[NE];                       // src[], permuted by segment

// ---------------- helpers ----------------
__device__ __forceinline__ unsigned fenc(float f) {
    unsigned u = __float_as_uint(f);
    return (u & 0x80000000u) ? ~u : (u | 0x80000000u);
}
__device__ __forceinline__ float fdec(unsigned u) {
    return (u & 0x80000000u) ? __uint_as_float(u & 0x7fffffffu) : __uint_as_float(~u);
}
__device__ __forceinline__ void bsplit(float w, __nv_bfloat16& hi, __nv_bfloat16& lo) {
    hi = __float2bfloat16(w);
    lo = __float2bfloat16(w - __bfloat162float(hi));
}
__device__ __forceinline__ void mma_bf16(float* c, unsigned a0, unsigned a1, unsigned a2,
                                         unsigned a3, unsigned b0, unsigned b1) {
    asm volatile(
        "mma.sync.aligned.m16n8k16.row.col.f32.bf16.bf16.f32 "
        "{%0,%1,%2,%3}, {%4,%5,%6,%7}, {%8,%9}, {%0,%1,%2,%3};\n"
        : "+f"(c[0]), "+f"(c[1]), "+f"(c[2]), "+f"(c[3])
        : "r"(a0), "r"(a1), "r"(a2), "r"(a3), "r"(b0), "r"(b1));
}
__device__ __forceinline__ void ldsm4(unsigned& r0, unsigned& r1, unsigned& r2, unsigned& r3,
                                      const void* p) {
    unsigned addr = (unsigned)__cvta_generic_to_shared(p);
    asm volatile("ldmatrix.sync.aligned.m8n8.x4.shared.b16 {%0,%1,%2,%3}, [%4];\n"
                 : "=r"(r0), "=r"(r1), "=r"(r2), "=r"(r3) : "r"(addr));
}
__device__ __forceinline__ void cp16(void* smem, const void* g, bool pred) {
    unsigned s = (unsigned)__cvta_generic_to_shared(smem);
    int sz = pred ? 16 : 0;
    asm volatile("cp.async.cg.shared.global [%0], [%1], 16, %2;\n" :: "r"(s), "l"(g), "r"(sz));
}

// ---------------- prep kernels ----------------
__global__ void prep_wext_kernel(const float* __restrict__ Wp, const float* __restrict__ Ws) {
    int idx = blockIdx.x * blockDim.x + threadIdx.x;
    if (idx >= CTOT * FIN) return;
    int c = idx >> 8, k = idx & 255;
    float w = (c < CPROJ) ? Wp[idx] : Ws[(c - CPROJ) * FIN + k];
    __nv_bfloat16 hi, lo; bsplit(w, hi, lo);
    size_t b = (size_t)c * 512;
    g_bext[b + k] = hi; g_bext[b + 256 + k] = lo;
}

__global__ void prep_aext_kernel(const float* __restrict__ x) {
    int idx = blockIdx.x * blockDim.x + threadIdx.x;
    int tot = NN * FIN;
    for (; idx < tot; idx += gridDim.x * blockDim.x) {
        int n = idx >> 8, k = idx & 255;
        float w = x[idx];
        __nv_bfloat16 hi, lo; bsplit(w, hi, lo);
        size_t b = (size_t)n * 512;
        g_aext[b + k] = hi; g_aext[b + 256 + k] = lo;
    }
}

// ---------------- K1: zero small scratch (counters + maxes) ----------------
__global__ void zero_kernel() {
    int idx = blockIdx.x * blockDim.x + threadIdx.x;
    for (int i = idx; i < NSEG; i += gridDim.x * blockDim.x) g_cnt[i] = 0;
    if (idx < NR * NH) g_m_u[idx] = 0u;
}

// ---------------- K2: bf16 TC GEMM, 3-pass split reuse + fused score epilogue ----------------
// C[N,1280] = x[N,256] @ Wcat^T in split-bf16:  hi*hi + lo*hi + hi*lo
// BM=128, BN=128; per 32-wide K chunk load A_hi/A_lo/B_hi/B_lo, 3 mma passes.
#define GSTR  40                         // smem row stride in halves (80B, conflict-free LDSM)
#define TILEB (128 * GSTR * 2)           // 10240 bytes per 128x32 tile
#define GSMEM (2 * 4 * TILEB + 128 * 4 * 4)   // 2 stages * 4 tiles + sred = 83968

__global__ void __launch_bounds__(256, 2) gemm_bf16_kernel(const float* __restrict__ sv_src,
                                                           const float* __restrict__ sv_trg) {
    extern __shared__ char gsm[];
    float* sred = (float*)(gsm + 2 * 4 * TILEB);

    int t = threadIdx.x;
    int lane = t & 31, w = t >> 5;
    int wm = w >> 2, wn = w & 3;           // wm 0..1 (64 rows), wn 0..3 (32 cols)
    int g = lane >> 2, tg = lane & 3;
    int row0 = blockIdx.y * 128;
    int col0 = blockIdx.x * 128;

    float acc[4][4][4];
#pragma unroll
    for (int i = 0; i < 4; i++)
#pragma unroll
        for (int j = 0; j < 4; j++)
#pragma unroll
            for (int q = 0; q < 4; q++) acc[i][j][q] = 0.f;

    auto tile = [&](int stage, int which) -> __nv_bfloat16* {
        return (__nv_bfloat16*)(gsm + (stage * 4 + which) * TILEB);
    };
    auto load_chunk = [&](int c, int s) {
        int k0 = c * 32;
#pragma unroll
        for (int i = 0; i < 2; i++) {
            int v = t + i * 256;          // 0..511 16B vectors per tile
            int row = v >> 2, kc = (v & 3) * 8;
            int ga = row0 + row;
            bool pa = ga < NN;
            int gac = pa ? ga : 0;
            const __nv_bfloat16* ap = g_aext + (size_t)gac * 512 + k0 + kc;
            cp16(tile(s, 0) + row * GSTR + kc, ap,       pa);   // A_hi
            cp16(tile(s, 1) + row * GSTR + kc, ap + 256, pa);   // A_lo
            const __nv_bfloat16* bp = g_bext + (size_t)(col0 + row) * 512 + k0 + kc;
            cp16(tile(s, 2) + row * GSTR + kc, bp,       true); // B_hi
            cp16(tile(s, 3) + row * GSTR + kc, bp + 256, true); // B_lo
        }
        asm volatile("cp.async.commit_group;\n");
    };

    load_chunk(0, 0);
    load_chunk(1, 1);

    for (int c = 0; c < 8; c++) {
        int s = c & 1;
        if (c < 7) asm volatile("cp.async.wait_group 1;\n");
        else       asm volatile("cp.async.wait_group 0;\n");
        __syncthreads();

        __nv_bfloat16* Ah = tile(s, 0);
        __nv_bfloat16* Al = tile(s, 1);
        __nv_bfloat16* Bh = tile(s, 2);
        __nv_bfloat16* Bl = tile(s, 3);

#pragma unroll
        for (int kk = 0; kk < 32; kk += 16) {
            int fr = lane & 15;
            int fc = kk + (lane >> 4) * 8;
            unsigned bh[2][4], bl[2][4];
#pragma unroll
            for (int np = 0; np < 2; np++) {
                int n = wn * 32 + np * 16 + fr;
                ldsm4(bh[np][0], bh[np][1], bh[np][2], bh[np][3], Bh + n * GSTR + fc);
                ldsm4(bl[np][0], bl[np][1], bl[np][2], bl[np][3], Bl + n * GSTR + fc);
            }
#pragma unroll
            for (int mt = 0; mt < 4; mt++) {
                int r = wm * 64 + mt * 16 + fr;
                unsigned ah0, ah1, ah2, ah3, al0, al1, al2, al3;
                ldsm4(ah0, ah1, ah2, ah3, Ah + r * GSTR + fc);
                ldsm4(al0, al1, al2, al3, Al + r * GSTR + fc);
#pragma unroll
                for (int nt = 0; nt < 4; nt++) {
                    int np = nt >> 1, sel = nt & 1;
                    unsigned b0 = bh[np][sel], b1 = bh[np][sel + 2];
                    mma_bf16(acc[mt][nt], ah0, ah1, ah2, ah3, b0, b1);   // hi*hi
                    mma_bf16(acc[mt][nt], al0, al1, al2, al3, b0, b1);   // lo*hi
                    unsigned c0 = bl[np][sel], c1 = bl[np][sel + 2];
                    mma_bf16(acc[mt][nt], ah0, ah1, ah2, ah3, c0, c1);   // hi*lo
                }
            }
        }
        __syncthreads();
        if (c + 2 < 8) load_chunk(c + 2, s);
    }

    // write proj/skip
#pragma unroll
    for (int mt = 0; mt < 4; mt++)
#pragma unroll
        for (int nt = 0; nt < 4; nt++) {
            int row = row0 + wm * 64 + mt * 16 + g;
            int col = col0 + wn * 32 + nt * 8 + tg * 2;
            if (row < NN) {
                float2 o = make_float2(acc[mt][nt][0], acc[mt][nt][1]);
                *reinterpret_cast<float2*>(g_ps + (size_t)row * CTOT + col) = o;
            }
            if (row + 8 < NN) {
                float2 o = make_float2(acc[mt][nt][2], acc[mt][nt][3]);
                *reinterpret_cast<float2*>(g_ps + (size_t)(row + 8) * CTOT + col) = o;
            }
        }

    // fused attention-score epilogue (only proj columns)
    if (col0 < CPROJ) {
        __syncthreads();
        for (int i = t; i < 512; i += 256) sred[i] = 0.f;
        __syncthreads();

        float sv[4][2], tv[4][2];
#pragma unroll
        for (int nt = 0; nt < 4; nt++)
#pragma unroll
            for (int qc = 0; qc < 2; qc++) {
                int cl = wn * 32 + nt * 8 + tg * 2 + qc;
                sv[nt][qc] = sv_src[col0 + cl];
                tv[nt][qc] = sv_trg[col0 + cl];
            }
        int p_idx = wn >> 1;   // 0 or 1 within the two 64-col slices of this block
#pragma unroll
        for (int mt = 0; mt < 4; mt++) {
            float s0 = 0.f, s1 = 0.f, t0 = 0.f, t1 = 0.f;
#pragma unroll
            for (int nt = 0; nt < 4; nt++)
#pragma unroll
                for (int qc = 0; qc < 2; qc++) {
                    s0 = fmaf(acc[mt][nt][qc],     sv[nt][qc], s0);
                    t0 = fmaf(acc[mt][nt][qc],     tv[nt][qc], t0);
                    s1 = fmaf(acc[mt][nt][2 + qc], sv[nt][qc], s1);
                    t1 = fmaf(acc[mt][nt][2 + qc], tv[nt][qc], t1);
                }
#pragma unroll
            for (int off = 1; off < 4; off <<= 1) {
                s0 += __shfl_xor_sync(0xffffffffu, s0, off);
                t0 += __shfl_xor_sync(0xffffffffu, t0, off);
                s1 += __shfl_xor_sync(0xffffffffu, s1, off);
                t1 += __shfl_xor_sync(0xffffffffu, t1, off);
            }
            if (tg == 0) {
                int r0 = wm * 64 + mt * 16 + g;
                atomicAdd(&sred[r0 * 4 + p_idx],           s0);
                atomicAdd(&sred[r0 * 4 + 2 + p_idx],       t0);
                atomicAdd(&sred[(r0 + 8) * 4 + p_idx],     s1);
                atomicAdd(&sred[(r0 + 8) * 4 + 2 + p_idx], t1);
            }
        }
        __syncthreads();
        int p0 = col0 >> 6;
        for (int i = t; i < 512; i += 256) {
            int row = i >> 2, j = i & 3;
            int n = row0 + row;
            if (n < NN) {
                float vval = sred[i];
                int p = p0 + (j & 1);
                if (j < 2) g_ssrc[n * 16 + p] = vval;
                else       g_strg[n * 16 + p] = vval;
            }
        }
    }
}

// ---------------- K4: edge pass 1 — per-(rel,head) max only ----------------
__global__ void __launch_bounds__(256) edge1_kernel(const int* __restrict__ src,
                                                    const int* __restrict__ trg,
                                                    const int* __restrict__ rel) {
    __shared__ unsigned sm[16];
    int t = threadIdx.x;
    if (t < 16) sm[t] = 0u;
    __syncthreads();
    int e = blockIdx.x * 256 + t;
    if (e < NE) {
        int r = rel[e];
        int is = src[e] * 16;
        int it = trg[e] * 16;
#pragma unroll
        for (int h = 0; h < NH; h++) {
            float v = g_ssrc[is + h * 4 + r] + g_strg[it + h * 4 + r];
            v = (v > 0.f) ? v : 0.2f * v;
            atomicMax(&sm[r * 4 + h], fenc(v));
        }
    }
    __syncthreads();
    if (t < 16 && sm[t] != 0u) atomicMax(&g_m_u[t], sm[t]);
}

// ---------------- counting sort: hist / scan x3 / scatter ----------------
__global__ void hist_kernel(const int* __restrict__ trg, const int* __restrict__ rel) {
    int e = blockIdx.x * 256 + threadIdx.x;
    if (e < NE) atomicAdd(&g_cnt[trg[e] * 4 + rel[e]], 1);
}

__global__ void __launch_bounds__(1024) scan1_kernel() {
    __shared__ int sd[1024];
    int t = threadIdx.x;
    int i = blockIdx.x * 1024 + t;
    int v = (i < NSEG) ? g_cnt[i] : 0;
    sd[t] = v;
    __syncthreads();
#pragma unroll
    for (int off = 1; off < 1024; off <<= 1) {
        int u = (t >= off) ? sd[t - off] : 0;
        __syncthreads();
        sd[t] += u;
        __syncthreads();
    }
    if (i < NSEG) g_off[i] = sd[t] - v;   // exclusive within block
    if (t == 1023) g_bsum[blockIdx.x] = sd[t];
}

__global__ void __launch_bounds__(256) scan2_kernel() {
    __shared__ int sd[256];
    int t = threadIdx.x;
    int v = (t < NB1) ? g_bsum[t] : 0;
    sd[t] = v;
    __syncthreads();
#pragma unroll
    for (int off = 1; off < 256; off <<= 1) {
        int u = (t >= off) ? sd[t - off] : 0;
        __syncthreads();
        sd[t] += u;
        __syncthreads();
    }
    if (t < NB1) g_bsum[t] = sd[t] - v;   // exclusive block bases
    if (t == 0) g_off[NSEG] = NE;
}

__global__ void __launch_bounds__(1024) scan3_kernel() {
    int i = blockIdx.x * 1024 + threadIdx.x;
    if (i < NSEG) {
        int o = g_off[i] + g_bsum[blockIdx.x];
        g_off[i] = o;
        g_cur[i] = o;
    }
}

__global__ void scatter_kernel(const int* __restrict__ src, const int* __restrict__ trg,
                               const int* __restrict__ rel) {
    int e = blockIdx.x * 256 + threadIdx.x;
    if (e >= NE) return;
    int seg = trg[e] * 4 + rel[e];
    int pos = atomicAdd(&g_cur[seg], 1);
    g_psrc[pos] = src[e];
}

// ---------------- K6: atomic-free segment aggregation (one warp per segment) ----------------
__global__ void __launch_bounds__(256) edge_agg_kernel() {
    int gw = (blockIdx.x * blockDim.x + threadIdx.x) >> 5;
    int lane = threadIdx.x & 31;
    if (gw >= NSEG) return;
    int seg = gw;
    int tg = seg >> 2, r = seg & 3;
    int beg = g_off[seg], end = g_off[seg + 1];

    float strg_h[4], m_h[4];
#pragma unroll
    for (int h = 0; h < 4; h++) {
        strg_h[h] = g_strg[tg * 16 + h * 4 + r];
        m_h[h]    = fdec(g_m_u[r * 4 + h]);
    }
    float num0[4] = {0.f, 0.f, 0.f, 0.f};
    float num1[4] = {0.f, 0.f, 0.f, 0.f};
    float den[4]  = {0.f, 0.f, 0.f, 0.f};

    for (int i = beg; i < end; i++) {
        int s = g_psrc[i];
        const float* pb = g_ps + (size_t)s * CTOT + r * 64;
        const float* sp = g_ssrc + s * 16 + r;
#pragma unroll
        for (int h = 0; h < 4; h++) {
            float v = sp[h * 4] + strg_h[h];
            v = (v > 0.f) ? v : 0.2f * v;
            float ex = expf(v - m_h[h]);
            den[h] += ex;
            const float* pp = pb + h * 256;
            num0[h] = fmaf(ex, pp[lane],      num0[h]);
            num1[h] = fmaf(ex, pp[lane + 32], num1[h]);
        }
    }
#pragma unroll
    for (int h = 0; h < 4; h++) {
        float inv = 1.f / (den[h] + 1e-16f);
        float* ag = g_agg + ((size_t)seg * 4 + h) * 64;
        ag[lane]      = num0[h] * inv;
        ag[lane + 32] = num1[h] * inv;
    }
}

// ---------------- K7: fused node kernel with tensor-core MLP ----------------
#define NS 200
#define NODE2_SMEM (128*NS*2*2 + 64*NS*2*2 + (64+64+64+128+128)*4)

__device__ __forceinline__ void mlp_layer(const __nv_bfloat16* __restrict__ Ain,
                                          const __nv_bfloat16* __restrict__ Wm,
                                          const float* __restrict__ bs,
                                          __nv_bfloat16* __restrict__ Hout, int t) {
    int lane = t & 31, w = t >> 5;
    int wm = w >> 2, wn = w & 3;
    int g = lane >> 2, tg = lane & 3;
    float acc[4][2][4];
#pragma unroll
    for (int i = 0; i < 4; i++)
#pragma unroll
        for (int j = 0; j < 2; j++)
#pragma unroll
            for (int q = 0; q < 4; q++) acc[i][j][q] = 0.f;

#pragma unroll
    for (int ks = 0; ks < 12; ks++) {
        int kk = ks * 16;
        unsigned af[4][4], bf_[2][2];
#pragma unroll
        for (int mt = 0; mt < 4; mt++) {
            const __nv_bfloat16* ap = Ain + (wm * 64 + mt * 16 + g) * NS + kk + tg * 2;
            af[mt][0] = *reinterpret_cast<const unsigned*>(ap);
            af[mt][1] = *reinterpret_cast<const unsigned*>(ap + 8 * NS);
            af[mt][2] = *reinterpret_cast<const unsigned*>(ap + 8);
            af[mt][3] = *reinterpret_cast<const unsigned*>(ap + 8 * NS + 8);
        }
#pragma unroll
        for (int nt = 0; nt < 2; nt++) {
            const __nv_bfloat16* bp = Wm + (wn * 16 + nt * 8 + g) * NS + kk + tg * 2;
            bf_[nt][0] = *reinterpret_cast<const unsigned*>(bp);
            bf_[nt][1] = *reinterpret_cast<const unsigned*>(bp + 8);
        }
#pragma unroll
        for (int mt = 0; mt < 4; mt++)
#pragma unroll
            for (int nt = 0; nt < 2; nt++)
                mma_bf16(acc[mt][nt], af[mt][0], af[mt][1], af[mt][2], af[mt][3],
                         bf_[nt][0], bf_[nt][1]);
    }
    __syncthreads();
#pragma unroll
    for (int mt = 0; mt < 4; mt++)
#pragma unroll
        for (int nt = 0; nt < 2; nt++) {
            int row = wm * 64 + mt * 16 + g;
            int col = wn * 16 + nt * 8 + tg * 2;
#pragma unroll
            for (int q = 0; q < 4; q++) {
                int rr = row + ((q >> 1) ? 8 : 0);
                int cc = col + (q & 1);
                float h = fmaxf(acc[mt][nt][q] + bs[cc], 0.f);
                __nv_bfloat16 hi, lo; bsplit(h, hi, lo);
                Hout[rr * NS + cc] = hi;
                Hout[rr * NS + 64 + cc] = lo;
                Hout[rr * NS + 128 + cc] = hi;
            }
        }
    __syncthreads();
}

__global__ void __launch_bounds__(256) node2_kernel(
        const float* __restrict__ W1, const float* __restrict__ b1,
        const float* __restrict__ W2, const float* __restrict__ b2,
        const float* __restrict__ W3, const float* __restrict__ b3,
        const float* __restrict__ bias, const float* __restrict__ gamma,
        const float* __restrict__ beta, float* __restrict__ out) {
    extern __shared__ char nsm[];
    __nv_bfloat16* Asp = reinterpret_cast<__nv_bfloat16*>(nsm);
    __nv_bfloat16* Hsp = Asp + 128 * NS;
    __nv_bfloat16* W1s = Hsp + 128 * NS;
    __nv_bfloat16* W2s = W1s + 64 * NS;
    float* W3s  = reinterpret_cast<float*>(W2s + 64 * NS);
    float* b1s  = W3s + 64;
    float* b2s  = b1s + 64;
    float* scs  = b2s + 64;
    float* alps = scs + 128;

    int t = threadIdx.x;
    int node0 = blockIdx.x * 8;

    for (int idx = t; idx < 4096; idx += 256) {
        int n_ = idx >> 6, k_ = idx & 63;
        __nv_bfloat16 hi, lo;
        bsplit(W1[idx], hi, lo);
        W1s[n_ * NS + k_] = hi; W1s[n_ * NS + 64 + k_] = hi; W1s[n_ * NS + 128 + k_] = lo;
        bsplit(W2[idx], hi, lo);
        W2s[n_ * NS + k_] = hi; W2s[n_ * NS + 64 + k_] = hi; W2s[n_ * NS + 128 + k_] = lo;
    }
    if (t < 64) { W3s[t] = W3[t]; b1s[t] = b1[t]; b2s[t] = b2[t]; }

    for (int idx = t; idx < 8192; idx += 256) {
        int row = idx >> 6, f = idx & 63;
        int ln = row >> 4, p = row & 15, h = p >> 2, r = p & 3;
        int n = node0 + ln;
        float a = g_agg[(((size_t)n * 4 + r) * 4 + h) * 64 + f];
        __nv_bfloat16 hi, lo; bsplit(a, hi, lo);
        Asp[row * NS + f] = hi; Asp[row * NS + 64 + f] = lo; Asp[row * NS + 128 + f] = hi;
    }
    __syncthreads();

    mlp_layer(Asp, W1s, b1s, Hsp, t);
    mlp_layer(Hsp, W2s, b2s, Hsp, t);

    if (t < 128) {
        float sacc = b3[0];
        const __nv_bfloat16* hp = Hsp + t * NS;
#pragma unroll
        for (int j = 0; j < 64; j++) {
            float hv = __bfloat162float(hp[j]) + __bfloat162float(hp[64 + j]);
            sacc = fmaf(hv, W3s[j], sacc);
        }
        float sp = (sacc > 20.f) ? sacc : log1pf(expf(sacc));
        scs[t] = sacc * tanhf(sp);
    }
    __syncthreads();

    if (t < 32) {
        int base = (t >> 2) * 16 + (t & 3) * 4;
        float mx = -1e30f;
#pragma unroll
        for (int r = 0; r < 4; r++) mx = fmaxf(mx, scs[base + r]);
        float ev[4], ssum = 0.f;
#pragma unroll
        for (int r = 0; r < 4; r++) { ev[r] = expf(scs[base + r] - mx); ssum += ev[r]; }
#pragma unroll
        for (int r = 0; r < 4; r++) alps[base + r] = ev[r] / ssum;
    }
    __syncthreads();

    // warp-per-node: weighted sum + skip + bias + ELU + LayerNorm
    int wid = t >> 5, lane = t & 31;
    int s = wid;
    int n = node0 + s;
    float os[8];
    float s1 = 0.f, s2 = 0.f;
#pragma unroll
    for (int c8 = 0; c8 < 8; c8++) {
        int col = c8 * 32 + lane;
        int hh = c8 >> 1;
        int f = (c8 & 1) * 32 + lane;
        int rb = s * 16 + hh * 4;
        float o = 0.f;
#pragma unroll
        for (int r = 0; r < 4; r++) {
            const __nv_bfloat16* ap = Asp + (rb + r) * NS;
            float a = __bfloat162float(ap[f]) + __bfloat162float(ap[64 + f]);
            o = fmaf(a, alps[rb + r], o);
        }
        o += g_ps[(size_t)n * CTOT + CPROJ + col];
        o += bias[col];
        o = (o > 0.f) ? o : expm1f(o);
        os[c8] = o;
        s1 += o;
        s2 += o * o;
    }
#pragma unroll
    for (int off = 16; off > 0; off >>= 1) {
        s1 += __shfl_xor_sync(0xffffffffu, s1, off);
        s2 += __shfl_xor_sync(0xffffffffu, s2, off);
    }
    float mu = s1 * (1.f / 256.f);
    float var = s2 * (1.f / 256.f) - mu * mu;
    float rstd = rsqrtf(var + 1e-5f);
#pragma unroll
    for (int c8 = 0; c8 < 8; c8++) {
        int col = c8 * 32 + lane;
        out[(size_t)n * 256 + col] = (os[c8] - mu) * rstd * gamma[col] + beta[col];
    }
}

// ---------------- launch ----------------
extern "C" void kernel_launch(void* const* d_in, const int* in_sizes, int n_in,
                              void* d_out, int out_size) {
    const float* x         = (const float*)d_in[0];
    const int*   src       = (const int*)d_in[1];
    const int*   trg       = (const int*)d_in[2];
    const int*   rel       = (const int*)d_in[3];
    // d_in[4] = node_to_graph_map (unused)
    const float* W_proj    = (const float*)d_in[5];
    const float* score_src = (const float*)d_in[6];
    const float* score_trg = (const float*)d_in[7];
    const float* W1        = (const float*)d_in[8];
    const float* b1        = (const float*)d_in[9];
    const float* W2        = (const float*)d_in[10];
    const float* b2        = (const float*)d_in[11];
    const float* W3        = (const float*)d_in[12];
    const float* b3        = (const float*)d_in[13];
    const float* W_skip    = (const float*)d_in[14];
    const float* bias      = (const float*)d_in[15];
    const float* gamma     = (const float*)d_in[16];
    const float* beta      = (const float*)d_in[17];
    float* out = (float*)d_out;

    cudaFuncSetAttribute(node2_kernel, cudaFuncAttributeMaxDynamicSharedMemorySize, NODE2_SMEM);
    cudaFuncSetAttribute(gemm_bf16_kernel, cudaFuncAttributeMaxDynamicSharedMemorySize, GSMEM);

    prep_wext_kernel<<<(CTOT * FIN + 511) / 512, 512>>>(W_proj, W_skip);
    prep_aext_kernel<<<8192, 256>>>(x);
    zero_kernel<<<784, 256>>>();

    dim3 ggrid(CTOT / 128, (NN + 127) / 128);
    gemm_bf16_kernel<<<ggrid, 256, GSMEM>>>(score_src, score_trg);

    int eb = (NE + 255) / 256;
    edge1_kernel<<<eb, 256>>>(src, trg, rel);

    // counting sort by (trg, rel)
    hist_kernel<<<eb, 256>>>(trg, rel);
    scan1_kernel<<<NB1, 1024>>>();
    scan2_kernel<<<1, 256>>>();
    scan3_kernel<<<NB1, 1024>>>();
    scatter_kernel<<<eb, 256>>>(src, trg, rel);

    // atomic-free aggregation
    edge_agg_kernel<<<(NSEG * 32 + 255) / 256, 256>>>();

    node2_kernel<<<NN / 8, 256, NODE2_SMEM>>>(W1, b1, W2, b2, W3, b3, bias, gamma, beta, out);
}

// round 7
// speedup vs baseline: 1.1763x; 1.1763x over previous
#include <cuda_runtime.h>
#include <cuda_bf16.h>
#include <math.h>

// Problem constants
#define NN     50000
#define FIN    256
#define NH     4
#define NR     4
#define FF     64
#define NE     500000
#define CPROJ  1024          // NH*NR*FF
#define CTOT   1280          // CPROJ + NH*FF (skip)
#define NSEG   (NN * NR)     // 200000 (trg, rel) segments
#define NB1    ((NSEG + 1023) / 1024)   // 196 scan blocks

// ---------------- scratch (device globals; no allocation allowed) ----------------
__device__ float         g_ps[(size_t)NN * CTOT];          // [n][1280]: proj | skip (fp32)
__device__ float         g_agg[(size_t)NN * NR * NH * FF]; // [((n*4+r)*4+h)*64+f]
__device__ float         g_ssrc[(size_t)NN * NH * NR];     // [n*16 + h*4 + r]
__device__ float         g_strg[(size_t)NN * NH * NR];
__device__ unsigned      g_m_u[NR * NH];
__device__ __nv_bfloat16 g_aext[(size_t)NN * 512];         // [n][512] = [x_hi(256) | x_lo(256)]
__device__ __nv_bfloat16 g_bext[(size_t)CTOT * 512];       // [c][512] = [W_hi | W_lo]
// edge sort scratch
__device__ int           g_cnt[NSEG];
__device__ int           g_off[NSEG + 1];
__device__ int           g_cur[NSEG];
__device__ int           g_bsum[256];
__device__ int           g_psrc[NE];                       // src[], permuted by segment

// ---------------- helpers ----------------
__device__ __forceinline__ unsigned fenc(float f) {
    unsigned u = __float_as_uint(f);
    return (u & 0x80000000u) ? ~u : (u | 0x80000000u);
}
__device__ __forceinline__ float fdec(unsigned u) {
    return (u & 0x80000000u) ? __uint_as_float(u & 0x7fffffffu) : __uint_as_float(~u);
}
__device__ __forceinline__ void bsplit(float w, __nv_bfloat16& hi, __nv_bfloat16& lo) {
    hi = __float2bfloat16(w);
    lo = __float2bfloat16(w - __bfloat162float(hi));
}
__device__ __forceinline__ void mma_bf16(float* c, unsigned a0, unsigned a1, unsigned a2,
                                         unsigned a3, unsigned b0, unsigned b1) {
    asm volatile(
        "mma.sync.aligned.m16n8k16.row.col.f32.bf16.bf16.f32 "
        "{%0,%1,%2,%3}, {%4,%5,%6,%7}, {%8,%9}, {%0,%1,%2,%3};\n"
        : "+f"(c[0]), "+f"(c[1]), "+f"(c[2]), "+f"(c[3])
        : "r"(a0), "r"(a1), "r"(a2), "r"(a3), "r"(b0), "r"(b1));
}
__device__ __forceinline__ void ldsm4(unsigned& r0, unsigned& r1, unsigned& r2, unsigned& r3,
                                      const void* p) {
    unsigned addr = (unsigned)__cvta_generic_to_shared(p);
    asm volatile("ldmatrix.sync.aligned.m8n8.x4.shared.b16 {%0,%1,%2,%3}, [%4];\n"
                 : "=r"(r0), "=r"(r1), "=r"(r2), "=r"(r3) : "r"(addr));
}

// ---------------- prep kernels ----------------
__global__ void prep_wext_kernel(const float* __restrict__ Wp, const float* __restrict__ Ws) {
    int idx = blockIdx.x * blockDim.x + threadIdx.x;
    if (idx >= CTOT * FIN) return;
    int c = idx >> 8, k = idx & 255;
    float w = (c < CPROJ) ? Wp[idx] : Ws[(c - CPROJ) * FIN + k];
    __nv_bfloat16 hi, lo; bsplit(w, hi, lo);
    size_t b = (size_t)c * 512;
    g_bext[b + k] = hi; g_bext[b + 256 + k] = lo;
}

__global__ void prep_aext_kernel(const float* __restrict__ x) {
    int idx = blockIdx.x * blockDim.x + threadIdx.x;
    int tot = NN * FIN;
    for (; idx < tot; idx += gridDim.x * blockDim.x) {
        int n = idx >> 8, k = idx & 255;
        float w = x[idx];
        __nv_bfloat16 hi, lo; bsplit(w, hi, lo);
        size_t b = (size_t)n * 512;
        g_aext[b + k] = hi; g_aext[b + 256 + k] = lo;
    }
}

// ---------------- K1: zero small scratch (counters + maxes) ----------------
__global__ void zero_kernel() {
    int idx = blockIdx.x * blockDim.x + threadIdx.x;
    for (int i = idx; i < NSEG; i += gridDim.x * blockDim.x) g_cnt[i] = 0;
    if (idx < NR * NH) g_m_u[idx] = 0u;
}

// ---------------- K2: bf16 TC GEMM v3 — static smem, ldmatrix, 3-pass split reuse ----------
// C[N,1280] = x[N,256] @ Wcat^T via split-bf16:  hi*hi + hi*lo + lo*hi
// BM=128, BN=128; 8 K-chunks of 32; fused attention-score epilogue.
#define GSTR 40   // smem row stride in halves (80B) — conflict-free ldmatrix
__global__ void __launch_bounds__(256) gemm_bf16_kernel(const float* __restrict__ sv_src,
                                                        const float* __restrict__ sv_trg) {
    __shared__ __nv_bfloat16 Ah[128 * GSTR];
    __shared__ __nv_bfloat16 Al[128 * GSTR];
    __shared__ __nv_bfloat16 Bh[128 * GSTR];
    __shared__ __nv_bfloat16 Bl[128 * GSTR];
    __shared__ float sred[512];

    int t = threadIdx.x;
    int lane = t & 31, w = t >> 5;
    int wm = w >> 2, wn = w & 3;           // wm 0..1 (64 rows), wn 0..3 (32 cols)
    int g = lane >> 2, tg = lane & 3;
    int row0 = blockIdx.y * 128;
    int col0 = blockIdx.x * 128;

    float acc[4][4][4];
#pragma unroll
    for (int i = 0; i < 4; i++)
#pragma unroll
        for (int j = 0; j < 4; j++)
#pragma unroll
            for (int q = 0; q < 4; q++) acc[i][j][q] = 0.f;

    // load geometry: 512 16B-vectors per 128x32 tile; thread covers rows r0 and r0+64
    int r0v = t >> 2;                 // 0..63
    int kcv = (t & 3) * 8;            // 0,8,16,24

    int fr = lane & 15;
    int fcb = (lane >> 4) * 8;

    for (int c = 0; c < 8; c++) {
        int k0 = c * 32;
        int ga0 = row0 + r0v, ga1 = row0 + r0v + 64;
        bool p0 = ga0 < NN, p1 = ga1 < NN;
        const __nv_bfloat16* ap0 = g_aext + (size_t)(p0 ? ga0 : 0) * 512 + k0 + kcv;
        const __nv_bfloat16* ap1 = g_aext + (size_t)(p1 ? ga1 : 0) * 512 + k0 + kcv;
        const __nv_bfloat16* bp0 = g_bext + (size_t)(col0 + r0v) * 512 + k0 + kcv;
        const __nv_bfloat16* bp1 = g_bext + (size_t)(col0 + r0v + 64) * 512 + k0 + kcv;
        float4 z = make_float4(0.f, 0.f, 0.f, 0.f);
        float4 ah0 = p0 ? *reinterpret_cast<const float4*>(ap0)       : z;
        float4 al0 = p0 ? *reinterpret_cast<const float4*>(ap0 + 256) : z;
        float4 ah1 = p1 ? *reinterpret_cast<const float4*>(ap1)       : z;
        float4 al1 = p1 ? *reinterpret_cast<const float4*>(ap1 + 256) : z;
        float4 bh0 = *reinterpret_cast<const float4*>(bp0);
        float4 bl0 = *reinterpret_cast<const float4*>(bp0 + 256);
        float4 bh1 = *reinterpret_cast<const float4*>(bp1);
        float4 bl1 = *reinterpret_cast<const float4*>(bp1 + 256);
        __syncthreads();
        *reinterpret_cast<float4*>(Ah + r0v * GSTR + kcv)        = ah0;
        *reinterpret_cast<float4*>(Ah + (r0v + 64) * GSTR + kcv) = ah1;
        *reinterpret_cast<float4*>(Al + r0v * GSTR + kcv)        = al0;
        *reinterpret_cast<float4*>(Al + (r0v + 64) * GSTR + kcv) = al1;
        *reinterpret_cast<float4*>(Bh + r0v * GSTR + kcv)        = bh0;
        *reinterpret_cast<float4*>(Bh + (r0v + 64) * GSTR + kcv) = bh1;
        *reinterpret_cast<float4*>(Bl + r0v * GSTR + kcv)        = bl0;
        *reinterpret_cast<float4*>(Bl + (r0v + 64) * GSTR + kcv) = bl1;
        __syncthreads();

#pragma unroll
        for (int kk = 0; kk < 32; kk += 16) {
            int fc = kk + fcb;
            unsigned bhf[2][4], blf[2][4];
#pragma unroll
            for (int np = 0; np < 2; np++) {
                int n = wn * 32 + np * 16 + fr;
                ldsm4(bhf[np][0], bhf[np][1], bhf[np][2], bhf[np][3], Bh + n * GSTR + fc);
                ldsm4(blf[np][0], blf[np][1], blf[np][2], blf[np][3], Bl + n * GSTR + fc);
            }
            // pass 1+2: A_hi against B_hi and B_lo
#pragma unroll
            for (int mt = 0; mt < 4; mt++) {
                int r = wm * 64 + mt * 16 + fr;
                unsigned a0, a1, a2, a3;
                ldsm4(a0, a1, a2, a3, Ah + r * GSTR + fc);
#pragma unroll
                for (int nt = 0; nt < 4; nt++) {
                    int np = nt >> 1, sel = nt & 1;
                    mma_bf16(acc[mt][nt], a0, a1, a2, a3, bhf[np][sel], bhf[np][sel + 2]);
                    mma_bf16(acc[mt][nt], a0, a1, a2, a3, blf[np][sel], blf[np][sel + 2]);
                }
            }
            // pass 3: A_lo against B_hi
#pragma unroll
            for (int mt = 0; mt < 4; mt++) {
                int r = wm * 64 + mt * 16 + fr;
                unsigned a0, a1, a2, a3;
                ldsm4(a0, a1, a2, a3, Al + r * GSTR + fc);
#pragma unroll
                for (int nt = 0; nt < 4; nt++) {
                    int np = nt >> 1, sel = nt & 1;
                    mma_bf16(acc[mt][nt], a0, a1, a2, a3, bhf[np][sel], bhf[np][sel + 2]);
                }
            }
        }
    }

    // write proj/skip
#pragma unroll
    for (int mt = 0; mt < 4; mt++)
#pragma unroll
        for (int nt = 0; nt < 4; nt++) {
            int row = row0 + wm * 64 + mt * 16 + g;
            int col = col0 + wn * 32 + nt * 8 + tg * 2;
            if (row < NN) {
                float2 o = make_float2(acc[mt][nt][0], acc[mt][nt][1]);
                *reinterpret_cast<float2*>(g_ps + (size_t)row * CTOT + col) = o;
            }
            if (row + 8 < NN) {
                float2 o = make_float2(acc[mt][nt][2], acc[mt][nt][3]);
                *reinterpret_cast<float2*>(g_ps + (size_t)(row + 8) * CTOT + col) = o;
            }
        }

    // fused attention-score epilogue (only proj columns)
    if (col0 < CPROJ) {
        __syncthreads();
        for (int i = t; i < 512; i += 256) sred[i] = 0.f;
        __syncthreads();

        float sv[4][2], tv[4][2];
#pragma unroll
        for (int nt = 0; nt < 4; nt++)
#pragma unroll
            for (int qc = 0; qc < 2; qc++) {
                int cl = wn * 32 + nt * 8 + tg * 2 + qc;
                sv[nt][qc] = sv_src[col0 + cl];
                tv[nt][qc] = sv_trg[col0 + cl];
            }
        int p_idx = wn >> 1;   // which of the two 64-col (h,r) slices in this block
#pragma unroll
        for (int mt = 0; mt < 4; mt++) {
            float s0 = 0.f, s1 = 0.f, t0 = 0.f, t1 = 0.f;
#pragma unroll
            for (int nt = 0; nt < 4; nt++)
#pragma unroll
                for (int qc = 0; qc < 2; qc++) {
                    s0 = fmaf(acc[mt][nt][qc],     sv[nt][qc], s0);
                    t0 = fmaf(acc[mt][nt][qc],     tv[nt][qc], t0);
                    s1 = fmaf(acc[mt][nt][2 + qc], sv[nt][qc], s1);
                    t1 = fmaf(acc[mt][nt][2 + qc], tv[nt][qc], t1);
                }
#pragma unroll
            for (int off = 1; off < 4; off <<= 1) {
                s0 += __shfl_xor_sync(0xffffffffu, s0, off);
                t0 += __shfl_xor_sync(0xffffffffu, t0, off);
                s1 += __shfl_xor_sync(0xffffffffu, s1, off);
                t1 += __shfl_xor_sync(0xffffffffu, t1, off);
            }
            if (tg == 0) {
                int r0 = wm * 64 + mt * 16 + g;
                atomicAdd(&sred[r0 * 4 + p_idx],           s0);
                atomicAdd(&sred[r0 * 4 + 2 + p_idx],       t0);
                atomicAdd(&sred[(r0 + 8) * 4 + p_idx],     s1);
                atomicAdd(&sred[(r0 + 8) * 4 + 2 + p_idx], t1);
            }
        }
        __syncthreads();
        int p0 = col0 >> 6;
        for (int i = t; i < 512; i += 256) {
            int row = i >> 2, j = i & 3;
            int n = row0 + row;
            if (n < NN) {
                float vval = sred[i];
                int p = p0 + (j & 1);
                if (j < 2) g_ssrc[n * 16 + p] = vval;
                else       g_strg[n * 16 + p] = vval;
            }
        }
    }
}

// ---------------- K4: edge pass 1 — per-(rel,head) max only ----------------
__global__ void __launch_bounds__(256) edge1_kernel(const int* __restrict__ src,
                                                    const int* __restrict__ trg,
                                                    const int* __restrict__ rel) {
    __shared__ unsigned sm[16];
    int t = threadIdx.x;
    if (t < 16) sm[t] = 0u;
    __syncthreads();
    int e = blockIdx.x * 256 + t;
    if (e < NE) {
        int r = rel[e];
        int is = src[e] * 16;
        int it = trg[e] * 16;
#pragma unroll
        for (int h = 0; h < NH; h++) {
            float v = g_ssrc[is + h * 4 + r] + g_strg[it + h * 4 + r];
            v = (v > 0.f) ? v : 0.2f * v;
            atomicMax(&sm[r * 4 + h], fenc(v));
        }
    }
    __syncthreads();
    if (t < 16 && sm[t] != 0u) atomicMax(&g_m_u[t], sm[t]);
}

// ---------------- counting sort: hist / scan x3 / scatter ----------------
__global__ void hist_kernel(const int* __restrict__ trg, const int* __restrict__ rel) {
    int e = blockIdx.x * 256 + threadIdx.x;
    if (e < NE) atomicAdd(&g_cnt[trg[e] * 4 + rel[e]], 1);
}

__global__ void __launch_bounds__(1024) scan1_kernel() {
    __shared__ int sd[1024];
    int t = threadIdx.x;
    int i = blockIdx.x * 1024 + t;
    int v = (i < NSEG) ? g_cnt[i] : 0;
    sd[t] = v;
    __syncthreads();
#pragma unroll
    for (int off = 1; off < 1024; off <<= 1) {
        int u = (t >= off) ? sd[t - off] : 0;
        __syncthreads();
        sd[t] += u;
        __syncthreads();
    }
    if (i < NSEG) g_off[i] = sd[t] - v;   // exclusive within block
    if (t == 1023) g_bsum[blockIdx.x] = sd[t];
}

__global__ void __launch_bounds__(256) scan2_kernel() {
    __shared__ int sd[256];
    int t = threadIdx.x;
    int v = (t < NB1) ? g_bsum[t] : 0;
    sd[t] = v;
    __syncthreads();
#pragma unroll
    for (int off = 1; off < 256; off <<= 1) {
        int u = (t >= off) ? sd[t - off] : 0;
        __syncthreads();
        sd[t] += u;
        __syncthreads();
    }
    if (t < NB1) g_bsum[t] = sd[t] - v;   // exclusive block bases
    if (t == 0) g_off[NSEG] = NE;
}

__global__ void __launch_bounds__(1024) scan3_kernel() {
    int i = blockIdx.x * 1024 + threadIdx.x;
    if (i < NSEG) {
        int o = g_off[i] + g_bsum[blockIdx.x];
        g_off[i] = o;
        g_cur[i] = o;
    }
}

__global__ void scatter_kernel(const int* __restrict__ src, const int* __restrict__ trg,
                               const int* __restrict__ rel) {
    int e = blockIdx.x * 256 + threadIdx.x;
    if (e >= NE) return;
    int seg = trg[e] * 4 + rel[e];
    int pos = atomicAdd(&g_cur[seg], 1);
    g_psrc[pos] = src[e];
}

// ---------------- K6: atomic-free segment aggregation (one warp per segment) ----------------
__global__ void __launch_bounds__(256) edge_agg_kernel() {
    int gw = (blockIdx.x * blockDim.x + threadIdx.x) >> 5;
    int lane = threadIdx.x & 31;
    if (gw >= NSEG) return;
    int seg = gw;
    int tg = seg >> 2, r = seg & 3;
    int beg = g_off[seg], end = g_off[seg + 1];

    float strg_h[4], m_h[4];
#pragma unroll
    for (int h = 0; h < 4; h++) {
        strg_h[h] = g_strg[tg * 16 + h * 4 + r];
        m_h[h]    = fdec(g_m_u[r * 4 + h]);
    }
    float num0[4] = {0.f, 0.f, 0.f, 0.f};
    float num1[4] = {0.f, 0.f, 0.f, 0.f};
    float den[4]  = {0.f, 0.f, 0.f, 0.f};

    for (int i = beg; i < end; i++) {
        int s = g_psrc[i];
        const float* pb = g_ps + (size_t)s * CTOT + r * 64;
        const float* sp = g_ssrc + s * 16 + r;
#pragma unroll
        for (int h = 0; h < 4; h++) {
            float v = sp[h * 4] + strg_h[h];
            v = (v > 0.f) ? v : 0.2f * v;
            float ex = expf(v - m_h[h]);
            den[h] += ex;
            const float* pp = pb + h * 256;
            num0[h] = fmaf(ex, pp[lane],      num0[h]);
            num1[h] = fmaf(ex, pp[lane + 32], num1[h]);
        }
    }
#pragma unroll
    for (int h = 0; h < 4; h++) {
        float inv = 1.f / (den[h] + 1e-16f);
        float* ag = g_agg + ((size_t)seg * 4 + h) * 64;
        ag[lane]      = num0[h] * inv;
        ag[lane + 32] = num1[h] * inv;
    }
}

// ---------------- K7: fused node kernel with tensor-core MLP ----------------
#define NS 200
#define NODE2_SMEM (128*NS*2*2 + 64*NS*2*2 + (64+64+64+128+128+32)*4)

__device__ __forceinline__ void mlp_layer(const __nv_bfloat16* __restrict__ Ain,
                                          const __nv_bfloat16* __restrict__ Wm,
                                          const float* __restrict__ bs,
                                          __nv_bfloat16* __restrict__ Hout, int t) {
    int lane = t & 31, w = t >> 5;
    int wm = w >> 2, wn = w & 3;
    int g = lane >> 2, tg = lane & 3;
    float acc[4][2][4];
#pragma unroll
    for (int i = 0; i < 4; i++)
#pragma unroll
        for (int j = 0; j < 2; j++)
#pragma unroll
            for (int q = 0; q < 4; q++) acc[i][j][q] = 0.f;

#pragma unroll
    for (int ks = 0; ks < 12; ks++) {
        int kk = ks * 16;
        unsigned af[4][4], bf_[2][2];
#pragma unroll
        for (int mt = 0; mt < 4; mt++) {
            const __nv_bfloat16* ap = Ain + (wm * 64 + mt * 16 + g) * NS + kk + tg * 2;
            af[mt][0] = *reinterpret_cast<const unsigned*>(ap);
            af[mt][1] = *reinterpret_cast<const unsigned*>(ap + 8 * NS);
            af[mt][2] = *reinterpret_cast<const unsigned*>(ap + 8);
            af[mt][3] = *reinterpret_cast<const unsigned*>(ap + 8 * NS + 8);
        }
#pragma unroll
        for (int nt = 0; nt < 2; nt++) {
            const __nv_bfloat16* bp = Wm + (wn * 16 + nt * 8 + g) * NS + kk + tg * 2;
            bf_[nt][0] = *reinterpret_cast<const unsigned*>(bp);
            bf_[nt][1] = *reinterpret_cast<const unsigned*>(bp + 8);
        }
#pragma unroll
        for (int mt = 0; mt < 4; mt++)
#pragma unroll
            for (int nt = 0; nt < 2; nt++)
                mma_bf16(acc[mt][nt], af[mt][0], af[mt][1], af[mt][2], af[mt][3],
                         bf_[nt][0], bf_[nt][1]);
    }
    __syncthreads();
#pragma unroll
    for (int mt = 0; mt < 4; mt++)
#pragma unroll
        for (int nt = 0; nt < 2; nt++) {
            int row = wm * 64 + mt * 16 + g;
            int col = wn * 16 + nt * 8 + tg * 2;
#pragma unroll
            for (int q = 0; q < 4; q++) {
                int rr = row + ((q >> 1) ? 8 : 0);
                int cc = col + (q & 1);
                float h = fmaxf(acc[mt][nt][q] + bs[cc], 0.f);
                __nv_bfloat16 hi, lo; bsplit(h, hi, lo);
                Hout[rr * NS + cc] = hi;
                Hout[rr * NS + 64 + cc] = lo;
                Hout[rr * NS + 128 + cc] = hi;
            }
        }
    __syncthreads();
}

__global__ void __launch_bounds__(256) node2_kernel(
        const float* __restrict__ W1, const float* __restrict__ b1,
        const float* __restrict__ W2, const float* __restrict__ b2,
        const float* __restrict__ W3, const float* __restrict__ b3,
        const float* __restrict__ bias, const float* __restrict__ gamma,
        const float* __restrict__ beta, float* __restrict__ out) {
    extern __shared__ char nsm[];
    __nv_bfloat16* Asp = reinterpret_cast<__nv_bfloat16*>(nsm);
    __nv_bfloat16* Hsp = Asp + 128 * NS;
    __nv_bfloat16* W1s = Hsp + 128 * NS;
    __nv_bfloat16* W2s = W1s + 64 * NS;
    float* W3s  = reinterpret_cast<float*>(W2s + 64 * NS);
    float* b1s  = W3s + 64;
    float* b2s  = b1s + 64;
    float* scs  = b2s + 64;
    float* alps = scs + 128;
    float* red  = alps + 128;

    int t = threadIdx.x;
    int node0 = blockIdx.x * 8;

    for (int idx = t; idx < 4096; idx += 256) {
        int n_ = idx >> 6, k_ = idx & 63;
        __nv_bfloat16 hi, lo;
        bsplit(W1[idx], hi, lo);
        W1s[n_ * NS + k_] = hi; W1s[n_ * NS + 64 + k_] = hi; W1s[n_ * NS + 128 + k_] = lo;
        bsplit(W2[idx], hi, lo);
        W2s[n_ * NS + k_] = hi; W2s[n_ * NS + 64 + k_] = hi; W2s[n_ * NS + 128 + k_] = lo;
    }
    if (t < 64) { W3s[t] = W3[t]; b1s[t] = b1[t]; b2s[t] = b2[t]; }

    for (int idx = t; idx < 8192; idx += 256) {
        int row = idx >> 6, f = idx & 63;
        int ln = row >> 4, p = row & 15, h = p >> 2, r = p & 3;
        int n = node0 + ln;
        float a = g_agg[(((size_t)n * 4 + r) * 4 + h) * 64 + f];
        __nv_bfloat16 hi, lo; bsplit(a, hi, lo);
        Asp[row * NS + f] = hi; Asp[row * NS + 64 + f] = lo; Asp[row * NS + 128 + f] = hi;
    }
    __syncthreads();

    mlp_layer(Asp, W1s, b1s, Hsp, t);
    mlp_layer(Hsp, W2s, b2s, Hsp, t);

    if (t < 128) {
        float sacc = b3[0];
        const __nv_bfloat16* hp = Hsp + t * NS;
#pragma unroll
        for (int j = 0; j < 64; j++) {
            float hv = __bfloat162float(hp[j]) + __bfloat162float(hp[64 + j]);
            sacc = fmaf(hv, W3s[j], sacc);
        }
        float sp = (sacc > 20.f) ? sacc : log1pf(expf(sacc));
        scs[t] = sacc * tanhf(sp);
    }
    __syncthreads();

    if (t < 32) {
        int base = (t >> 2) * 16 + (t & 3) * 4;
        float mx = -1e30f;
#pragma unroll
        for (int r = 0; r < 4; r++) mx = fmaxf(mx, scs[base + r]);
        float ev[4], ssum = 0.f;
#pragma unroll
        for (int r = 0; r < 4; r++) { ev[r] = expf(scs[base + r] - mx); ssum += ev[r]; }
#pragma unroll
        for (int r = 0; r < 4; r++) alps[base + r] = ev[r] / ssum;
    }
    __syncthreads();

    int hh = t >> 6, f = t & 63;
    int wid = t >> 5, lane = t & 31;
#pragma unroll 1
    for (int s = 0; s < 8; s++) {
        int n = node0 + s;
        int rb = s * 16 + hh * 4;
        float o = 0.f;
#pragma unroll
        for (int r = 0; r < 4; r++) {
            const __nv_bfloat16* ap = Asp + (rb + r) * NS;
            float a = __bfloat162float(ap[f]) + __bfloat162float(ap[64 + f]);
            o = fmaf(a, alps[rb + r], o);
        }
        o += g_ps[(size_t)n * CTOT + CPROJ + t];
        o += bias[t];
        o = (o > 0.f) ? o : expm1f(o);

        float s1 = o, s2 = o * o;
#pragma unroll
        for (int off = 16; off > 0; off >>= 1) {
            s1 += __shfl_down_sync(0xffffffffu, s1, off);
            s2 += __shfl_down_sync(0xffffffffu, s2, off);
        }
        if (lane == 0) { red[wid] = s1; red[8 + wid] = s2; }
        __syncthreads();
        if (t == 0) {
            float S1 = 0.f, S2 = 0.f;
#pragma unroll
            for (int w = 0; w < 8; w++) { S1 += red[w]; S2 += red[8 + w]; }
            float mu = S1 * (1.f / 256.f);
            float var = S2 * (1.f / 256.f) - mu * mu;
            red[16] = mu;
            red[17] = rsqrtf(var + 1e-5f);
        }
        __syncthreads();
        float mu = red[16], rstd = red[17];
        out[(size_t)n * 256 + t] = (o - mu) * rstd * gamma[t] + beta[t];
        __syncthreads();
    }
}

// ---------------- launch ----------------
extern "C" void kernel_launch(void* const* d_in, const int* in_sizes, int n_in,
                              void* d_out, int out_size) {
    const float* x         = (const float*)d_in[0];
    const int*   src       = (const int*)d_in[1];
    const int*   trg       = (const int*)d_in[2];
    const int*   rel       = (const int*)d_in[3];
    // d_in[4] = node_to_graph_map (unused)
    const float* W_proj    = (const float*)d_in[5];
    const float* score_src = (const float*)d_in[6];
    const float* score_trg = (const float*)d_in[7];
    const float* W1        = (const float*)d_in[8];
    const float* b1        = (const float*)d_in[9];
    const float* W2        = (const float*)d_in[10];
    const float* b2        = (const float*)d_in[11];
    const float* W3        = (const float*)d_in[12];
    const float* b3        = (const float*)d_in[13];
    const float* W_skip    = (const float*)d_in[14];
    const float* bias      = (const float*)d_in[15];
    const float* gamma     = (const float*)d_in[16];
    const float* beta      = (const float*)d_in[17];
    float* out = (float*)d_out;

    cudaFuncSetAttribute(node2_kernel, cudaFuncAttributeMaxDynamicSharedMemorySize, NODE2_SMEM);

    prep_wext_kernel<<<(CTOT * FIN + 511) / 512, 512>>>(W_proj, W_skip);
    prep_aext_kernel<<<8192, 256>>>(x);
    zero_kernel<<<784, 256>>>();

    dim3 ggrid(CTOT / 128, (NN + 127) / 128);
    gemm_bf16_kernel<<<ggrid, 256>>>(score_src, score_trg);

    int eb = (NE + 255) / 256;
    edge1_kernel<<<eb, 256>>>(src, trg, rel);

    // counting sort by (trg, rel)
    hist_kernel<<<eb, 256>>>(trg, rel);
    scan1_kernel<<<NB1, 1024>>>();
    scan2_kernel<<<1, 256>>>();
    scan3_kernel<<<NB1, 1024>>>();
    scatter_kernel<<<eb, 256>>>(src, trg, rel);

    // atomic-free aggregation
    edge_agg_kernel<<<(NSEG * 32 + 255) / 256, 256>>>();

    node2_kernel<<<NN / 8, 256, NODE2_SMEM>>>(W1, b1, W2, b2, W3, b3, bias, gamma, beta, out);
}